// round 1
// baseline (speedup 1.0000x reference)
#include <cuda_runtime.h>
#include <cstdint>

// Unpool (stride-2 zero insertion):
//   in : (B, C, 112, 112) fp32, contiguous
//   out: (B, C, 224, 224) fp32, out[..., ::2, ::2] = in, else 0
//
// Strategy: one float4 (16B) store per thread across the entire output.
// Global output row r (over B*C*224 rows) is an even row iff (r & 1) == 0,
// and since H_OUT = 2*H_IN, the matching global input row is simply r >> 1.
// Even rows interleave: [x0, 0, x1, 0] -> one float2 load per float4 store.

namespace {
constexpr int W_IN   = 112;
constexpr int H_IN   = 112;
constexpr int W_OUT  = 224;
constexpr int W4_OUT = W_OUT / 4;   // 56 float4 per output row
constexpr int W2_IN  = W_IN / 2;    // 56 float2 per input row
}

__global__ void unpool_kernel(const float2* __restrict__ x2,
                              float4* __restrict__ out,
                              int total4)
{
    int idx = blockIdx.x * blockDim.x + threadIdx.x;
    if (idx >= total4) return;

    int row = idx / W4_OUT;          // global output row (img*224 + oh)
    int c4  = idx - row * W4_OUT;    // float4 column within row

    float4 v;
    if (row & 1) {
        v = make_float4(0.f, 0.f, 0.f, 0.f);
    } else {
        // row even: global input row = row >> 1 (== img*112 + ih)
        float2 a = x2[(row >> 1) * W2_IN + c4];
        v = make_float4(a.x, 0.f, a.y, 0.f);
    }
    out[idx] = v;
}

extern "C" void kernel_launch(void* const* d_in, const int* in_sizes, int n_in,
                              void* d_out, int out_size)
{
    const float2* x2 = (const float2*)d_in[0];
    float4* out = (float4*)d_out;

    // out_size = B*C*224*224 floats; one thread per float4
    int total4 = out_size / 4;

    const int threads = 256;
    int blocks = (total4 + threads - 1) / threads;
    unpool_kernel<<<blocks, threads>>>(x2, out, total4);
}

// round 2
// speedup vs baseline: 1.1575x; 1.1575x over previous
#include <cuda_runtime.h>
#include <cstdint>

// Unpool (stride-2 zero insertion):
//   in : (B, C, 112, 112) fp32, contiguous
//   out: (B, C, 224, 224) fp32, out[..., ::2, ::2] = in, else 0
//
// One thread per (global input row, float4 column within the output row).
// Each thread:
//   - loads one float2 from the input row (streaming hint),
//   - stores [x0, 0, x1, 0] to the even output row,
//   - stores [0, 0, 0, 0]   to the following odd output row.
// Control flow is fully uniform (no even/odd branch), all accesses coalesced.

namespace {
constexpr int W4_OUT = 56;   // float4 per 224-wide output row
constexpr int W2_IN  = 56;   // float2 per 112-wide input row
}

__global__ void __launch_bounds__(256)
unpool_kernel(const float2* __restrict__ x2,
              float4* __restrict__ out,
              int total)              // total = global_input_rows * 56
{
    int idx = blockIdx.x * blockDim.x + threadIdx.x;
    if (idx >= total) return;

    int irow = idx / W4_OUT;          // global input row (img*112 + ih)
    int c4   = idx - irow * W4_OUT;   // float4 column

    // streaming load: read-once
    float2 a = __ldcs(&x2[irow * W2_IN + c4]);

    float4* even = out + (size_t)(2 * irow)     * W4_OUT + c4;
    float4* odd  = out + (size_t)(2 * irow + 1) * W4_OUT + c4;

    // streaming stores: write-once, evict-first
    __stcs(even, make_float4(a.x, 0.f, a.y, 0.f));
    __stcs(odd,  make_float4(0.f, 0.f, 0.f, 0.f));
}

extern "C" void kernel_launch(void* const* d_in, const int* in_sizes, int n_in,
                              void* d_out, int out_size)
{
    const float2* x2 = (const float2*)d_in[0];
    float4* out = (float4*)d_out;

    // out_size = B*C*224*224 floats. Input rows * 56 = out_size / 8.
    int total = out_size / 8;

    const int threads = 256;
    int blocks = (total + threads - 1) / threads;
    unpool_kernel<<<blocks, threads>>>(x2, out, total);
}